// round 1
// baseline (speedup 1.0000x reference)
#include <cuda_runtime.h>
#include <cuda_bf16.h>
#include <math.h>

// ---------------- problem constants ----------------
#define B_ 512
#define D_ 512
#define C_ 100000

#define S_F    30.0f
#define COSM_F 0.8775825618903728f
#define SINM_F 0.479425538604203f
#define TH_F  (-0.8775825618903728f)
#define MM_F   0.2397127693021015f

// ---------------- device scratch (no allocation allowed) ----------------
__device__ float g_inv_nx[B_];
__device__ float g_inv_nw[C_];
__device__ int   g_label[B_];

// ---------------- label decode: handles int64 or int32 layout ----------------
// Reads only the first 512 int32 words (2048 B, safe under either dtype).
// If the buffer is int64, every odd word (high half of values < 100000) is 0.
__global__ void decode_labels_kernel(const int* __restrict__ raw) {
    __shared__ int any_odd_nonzero;
    int t = threadIdx.x;  // 512 threads
    if (t == 0) any_odd_nonzero = 0;
    __syncthreads();
    int w = raw[t];
    if ((t & 1) && (w != 0)) any_odd_nonzero = 1;  // benign race
    __syncthreads();
    // int64 layout: label[t] lives at word 2*t (max index 1022 < 1024, in-bounds
    // only when the buffer really is int64 — guaranteed by the detection).
    g_label[t] = any_odd_nonzero ? raw[t] : raw[2 * t];
}

// ---------------- row inverse norms (D_ = 512, one block per row) ----------------
// which: 0 -> g_inv_nx, 1 -> g_inv_nw
__global__ void row_inv_norm_kernel(const float* __restrict__ x, int rows, int which) {
    int row = blockIdx.x;
    if (row >= rows) return;
    int t = threadIdx.x;  // 128 threads, 512/4 = 128 float4 per row
    const float4* p = reinterpret_cast<const float4*>(x + (size_t)row * D_);
    float4 v = p[t];
    float s = v.x * v.x + v.y * v.y + v.z * v.z + v.w * v.w;
#pragma unroll
    for (int o = 16; o > 0; o >>= 1) s += __shfl_xor_sync(0xffffffffu, s, o);
    __shared__ float ws[4];
    if ((t & 31) == 0) ws[t >> 5] = s;
    __syncthreads();
    if (t == 0) {
        float tot = ws[0] + ws[1] + ws[2] + ws[3];
        float inv = 1.0f / fmaxf(sqrtf(tot), 1e-12f);
        if (which == 0) g_inv_nx[row] = inv;
        else            g_inv_nw[row] = inv;
    }
}

// ---------------- fused SGEMM + ArcFace epilogue ----------------
// C[m,n] = sum_k X[m,k] * W[n,k]   (both K-contiguous, NT layout)
// BM=BN=128, BK=8, 256 threads, 8x8 per-thread microtile.
#define BM 128
#define BN 128
#define BK 8

__global__ __launch_bounds__(256)
void arcface_gemm_kernel(const float* __restrict__ X,
                         const float* __restrict__ W,
                         float* __restrict__ out) {
    __shared__ float As[BK][BM];
    __shared__ float Bs[BK][BN];

    const int tid = threadIdx.x;
    const int tx  = tid & 15;   // n direction (16)
    const int ty  = tid >> 4;   // m direction (16)
    const int m0  = blockIdx.y * BM;
    const int n0  = blockIdx.x * BN;

    // global->smem load mapping: each thread loads one float4 from A and one from B
    const int lrow = tid >> 1;         // 0..127
    const int lcol = (tid & 1) << 2;   // 0 or 4

    const float* Aptr = X + (size_t)(m0 + lrow) * D_ + lcol;
    const bool   bok  = (n0 + lrow) < C_;
    const float* Bptr = W + (size_t)(bok ? (n0 + lrow) : 0) * D_ + lcol;

    float acc[8][8];
#pragma unroll
    for (int i = 0; i < 8; i++)
#pragma unroll
        for (int j = 0; j < 8; j++) acc[i][j] = 0.0f;

    for (int k0 = 0; k0 < D_; k0 += BK) {
        float4 av = *reinterpret_cast<const float4*>(Aptr + k0);
        float4 bv = make_float4(0.f, 0.f, 0.f, 0.f);
        if (bok) bv = *reinterpret_cast<const float4*>(Bptr + k0);

        As[lcol + 0][lrow] = av.x;
        As[lcol + 1][lrow] = av.y;
        As[lcol + 2][lrow] = av.z;
        As[lcol + 3][lrow] = av.w;
        Bs[lcol + 0][lrow] = bv.x;
        Bs[lcol + 1][lrow] = bv.y;
        Bs[lcol + 2][lrow] = bv.z;
        Bs[lcol + 3][lrow] = bv.w;
        __syncthreads();

#pragma unroll
        for (int k = 0; k < BK; k++) {
            float4 a0 = *reinterpret_cast<const float4*>(&As[k][ty * 8]);
            float4 a1 = *reinterpret_cast<const float4*>(&As[k][ty * 8 + 4]);
            float4 b0 = *reinterpret_cast<const float4*>(&Bs[k][tx * 8]);
            float4 b1 = *reinterpret_cast<const float4*>(&Bs[k][tx * 8 + 4]);
            float af[8] = {a0.x, a0.y, a0.z, a0.w, a1.x, a1.y, a1.z, a1.w};
            float bf[8] = {b0.x, b0.y, b0.z, b0.w, b1.x, b1.y, b1.z, b1.w};
#pragma unroll
            for (int i = 0; i < 8; i++)
#pragma unroll
                for (int j = 0; j < 8; j++) acc[i][j] += af[i] * bf[j];
        }
        __syncthreads();
    }

    // ---------------- epilogue ----------------
    float invx[8];
    int   lab[8];
#pragma unroll
    for (int i = 0; i < 8; i++) {
        int m = m0 + ty * 8 + i;
        invx[i] = g_inv_nx[m];
        lab[i]  = g_label[m];
    }

    const int ncol = n0 + tx * 8;
#pragma unroll
    for (int i = 0; i < 8; i++) {
        int m = m0 + ty * 8 + i;
        float* orow = out + (size_t)m * C_ + ncol;
#pragma unroll
        for (int j = 0; j < 8; j++) {
            int n = ncol + j;
            if (n < C_) {
                float c = acc[i][j] * invx[i] * g_inv_nw[n];
                c = fminf(1.0f, fmaxf(-1.0f, c));
                float s2 = fminf(1.0f, fmaxf(1e-9f, 1.0f - c * c));
                float s  = sqrtf(s2);
                float phi = c * COSM_F - s * SINM_F;
                if (!(c > TH_F)) phi = c - MM_F;
                float r = (n == lab[i]) ? phi : c;
                orow[j] = r * S_F;
            }
        }
    }
}

// ---------------- launch ----------------
extern "C" void kernel_launch(void* const* d_in, const int* in_sizes, int n_in,
                              void* d_out, int out_size) {
    const float* X = nullptr;
    const float* W = nullptr;
    const void*  L = nullptr;

    for (int i = 0; i < n_in; i++) {
        int s = in_sizes[i];
        if (s == B_ * D_)      X = (const float*)d_in[i];
        else if (s == C_ * D_) W = (const float*)d_in[i];
        else if (s == B_)      L = d_in[i];
    }
    // fallback to metadata order: input, label, weight
    if (!X) X = (const float*)d_in[0];
    if (!L) L = d_in[1];
    if (!W) W = (const float*)d_in[2];

    float* out = (float*)d_out;

    decode_labels_kernel<<<1, 512>>>((const int*)L);
    row_inv_norm_kernel<<<B_, 128>>>(X, B_, 0);
    row_inv_norm_kernel<<<C_, 128>>>(W, C_, 1);

    dim3 grid((C_ + BN - 1) / BN, B_ / BM);
    arcface_gemm_kernel<<<grid, 256>>>(X, W, out);
    (void)out_size;
}

// round 3
// speedup vs baseline: 3.2448x; 3.2448x over previous
#include <cuda_runtime.h>
#include <cuda_bf16.h>
#include <math.h>
#include <stdint.h>

// ---------------- problem constants ----------------
#define B_ 512
#define D_ 512
#define C_ 100000

#define S_F    30.0f
#define COSM_F 0.8775825618903728f
#define SINM_F 0.479425538604203f
#define TH_F  (-0.8775825618903728f)
#define MM_F   0.2397127693021015f

// ---------------- device scratch (static globals: allowed) ----------------
__device__ __nv_bfloat16 g_Xhi[B_ * D_];
__device__ __nv_bfloat16 g_Xlo[B_ * D_];
__device__ __nv_bfloat16 g_Whi[(size_t)C_ * D_];
__device__ __nv_bfloat16 g_Wlo[(size_t)C_ * D_];
__device__ int g_label[B_];

// ---------------- helpers ----------------
__device__ __forceinline__ uint32_t smem_u32(const void* p) {
    uint32_t a;
    asm("{ .reg .u64 t; cvta.to.shared.u64 t, %1; cvt.u32.u64 %0, t; }" : "=r"(a) : "l"(p));
    return a;
}

// bf16 "hi" part (RNE), returns hi as float, hi bits in top 16 of hibits
__device__ __forceinline__ float bf16_hi_f(float f, uint32_t& hibits) {
    uint32_t u = __float_as_uint(f);
    hibits = (u + 0x7FFFu + ((u >> 16) & 1u)) & 0xFFFF0000u;
    return __uint_as_float(hibits);
}

__device__ __forceinline__ uint32_t pack_bf16x2(float f0, float f1) {
    uint32_t r;
    asm("cvt.rn.bf16x2.f32 %0, %1, %2;" : "=r"(r) : "f"(f1), "f"(f0));
    return r;
}

#define CP16(sm, gp, sz) \
    asm volatile("cp.async.cg.shared.global [%0], [%1], 16, %2;" \
                 :: "r"(sm), "l"(gp), "r"(sz) : "memory")

#define LDSM4(r, addr) \
    asm volatile("ldmatrix.sync.aligned.m8n8.x4.shared.b16 {%0,%1,%2,%3}, [%4];" \
                 : "=r"((r)[0]), "=r"((r)[1]), "=r"((r)[2]), "=r"((r)[3]) : "r"(addr))

#define MMA(acc, a, b) \
    asm volatile("mma.sync.aligned.m16n8k16.row.col.f32.bf16.bf16.f32 " \
                 "{%0,%1,%2,%3},{%4,%5,%6,%7},{%8,%9},{%0,%1,%2,%3};" \
                 : "+f"((acc)[0]), "+f"((acc)[1]), "+f"((acc)[2]), "+f"((acc)[3]) \
                 : "r"((a)[0]), "r"((a)[1]), "r"((a)[2]), "r"((a)[3]), \
                   "r"((b)[0]), "r"((b)[1]))

__device__ __forceinline__ float arcf(float c, bool isl) {
    c = fminf(1.0f, fmaxf(-1.0f, c));
    float s2 = fminf(1.0f, fmaxf(1e-9f, 1.0f - c * c));
    float sn;
    asm("sqrt.approx.f32 %0, %1;" : "=f"(sn) : "f"(s2));
    float phi = c * COSM_F - sn * SINM_F;
    phi = (c > TH_F) ? phi : (c - MM_F);
    return (isl ? phi : c) * S_F;
}

// ---------------- label decode (int64 or int32 layout) ----------------
__global__ void decode_labels_kernel(const int* __restrict__ raw) {
    __shared__ int any_odd_nonzero;
    int t = threadIdx.x;  // 512
    if (t == 0) any_odd_nonzero = 0;
    __syncthreads();
    int w = raw[t];
    if ((t & 1) && (w != 0)) any_odd_nonzero = 1;
    __syncthreads();
    g_label[t] = any_odd_nonzero ? raw[t] : raw[2 * t];
}

// ---------------- X: normalize + bf16 hi/lo split ----------------
__global__ void xprep_kernel(const float* __restrict__ X) {
    int row = blockIdx.x;
    int t = threadIdx.x;  // 128
    const float4* xf = reinterpret_cast<const float4*>(X + (size_t)row * D_);
    float4 v = xf[t];
    float s = v.x * v.x + v.y * v.y + v.z * v.z + v.w * v.w;
#pragma unroll
    for (int o = 16; o > 0; o >>= 1) s += __shfl_xor_sync(0xffffffffu, s, o);
    __shared__ float ws[4];
    if ((t & 31) == 0) ws[t >> 5] = s;
    __syncthreads();
    float tot = ws[0] + ws[1] + ws[2] + ws[3];
    float inv = 1.0f / fmaxf(sqrtf(tot), 1e-12f);
    float a0 = v.x * inv, a1 = v.y * inv, a2 = v.z * inv, a3 = v.w * inv;
    uint32_t h0, h1, h2, h3;
    float hf0 = bf16_hi_f(a0, h0), hf1 = bf16_hi_f(a1, h1);
    float hf2 = bf16_hi_f(a2, h2), hf3 = bf16_hi_f(a3, h3);
    uint2 hv, lv;
    hv.x = __byte_perm(h0, h1, 0x7632);
    hv.y = __byte_perm(h2, h3, 0x7632);
    lv.x = pack_bf16x2(a0 - hf0, a1 - hf1);
    lv.y = pack_bf16x2(a2 - hf2, a3 - hf3);
    size_t byt = ((size_t)row * D_ + t * 4) * 2;
    *reinterpret_cast<uint2*>((char*)g_Xhi + byt) = hv;
    *reinterpret_cast<uint2*>((char*)g_Xlo + byt) = lv;
}

// ---------------- W: normalize + bf16 hi/lo split (2 rows per block) ---------
__global__ __launch_bounds__(256)
void wprep_kernel(const float* __restrict__ W) {
    int h = threadIdx.x >> 7;          // 0/1: which row
    int t = threadIdx.x & 127;         // 128 threads per row
    int row = blockIdx.x * 2 + h;      // C_ is even, grid = C_/2 -> always valid
    const float4* wf = reinterpret_cast<const float4*>(W + (size_t)row * D_);
    float4 v = wf[t];
    float s = v.x * v.x + v.y * v.y + v.z * v.z + v.w * v.w;
#pragma unroll
    for (int o = 16; o > 0; o >>= 1) s += __shfl_xor_sync(0xffffffffu, s, o);
    __shared__ float ws[8];
    if ((t & 31) == 0) ws[h * 4 + (t >> 5)] = s;
    __syncthreads();
    float tot = ws[h * 4 + 0] + ws[h * 4 + 1] + ws[h * 4 + 2] + ws[h * 4 + 3];
    float inv = 1.0f / fmaxf(sqrtf(tot), 1e-12f);
    float a0 = v.x * inv, a1 = v.y * inv, a2 = v.z * inv, a3 = v.w * inv;
    uint32_t h0, h1, h2, h3;
    float hf0 = bf16_hi_f(a0, h0), hf1 = bf16_hi_f(a1, h1);
    float hf2 = bf16_hi_f(a2, h2), hf3 = bf16_hi_f(a3, h3);
    uint2 hv, lv;
    hv.x = __byte_perm(h0, h1, 0x7632);
    hv.y = __byte_perm(h2, h3, 0x7632);
    lv.x = pack_bf16x2(a0 - hf0, a1 - hf1);
    lv.y = pack_bf16x2(a2 - hf2, a3 - hf3);
    size_t byt = ((size_t)row * D_ + t * 4) * 2;
    *reinterpret_cast<uint2*>((char*)g_Whi + byt) = hv;
    *reinterpret_cast<uint2*>((char*)g_Wlo + byt) = lv;
}

// ---------------- GEMM + ArcFace (mma.sync bf16 3-product) ----------------
// CTA 128x128, BK=64 bf16 (128B rows, SW128 swizzle), 3-stage cp.async pipeline.
#define AHI_OFF 0
#define ALO_OFF 16384
#define BHI_OFF 32768
#define BLO_OFF 49152
#define STAGE_SZ 65536
#define NSTAGE 3
#define SMEM_TOTAL (NSTAGE * STAGE_SZ)   // 196608

__global__ __launch_bounds__(256, 1)
void arcface_mma_kernel(float* __restrict__ out) {
    extern __shared__ char Smem[];
    __shared__ int slab[128];
    const uint32_t sb = smem_u32(Smem);
    const int tid = threadIdx.x;
    const int lane = tid & 31;
    const int wid = tid >> 5;
    const int m0 = blockIdx.x * 128;   // x fastest -> 4 m-tiles share W n-tile in L2
    const int n0 = blockIdx.y * 128;
    const int mW = (wid >> 2) * 64;    // warp tile 64x32
    const int nW = (wid & 3) * 32;

    if (tid < 128) slab[tid] = g_label[m0 + tid];

    float acc[4][4][4];
#pragma unroll
    for (int i = 0; i < 4; i++)
#pragma unroll
        for (int j = 0; j < 4; j++)
#pragma unroll
            for (int q = 0; q < 4; q++) acc[i][j][q] = 0.0f;

    // producer mapping (per 16B chunk): idx -> row idx>>3, chunk idx&7
    const int pr = tid >> 1;                 // not used; see loop below

    // ldmatrix lane-address components
    const int arow = mW + (lane & 7) + ((lane >> 3) & 1) * 8;   // + 16*i
    const int acol = ((lane >> 4) & 1) * 16;                    // + 32*g
    const int brow = nW + ((lane >> 4) & 1) * 8 + (lane & 7);   // + 16*jp
    const int bcol = ((lane >> 3) & 1) * 16;
    const int sx   = (lane & 7) * 16;                           // swizzle xor

    auto load_stage = [&](int kc, int st) {
        uint32_t base = sb + st * STAGE_SZ;
#pragma unroll
        for (int j = 0; j < 4; j++) {
            int idx = tid + 256 * j;
            int r = idx >> 3, c = idx & 7;
            uint32_t doff = (uint32_t)(r * 128 + ((c * 16) ^ ((r & 7) * 16)));
            size_t abyt = (size_t)(m0 + r) * (D_ * 2) + kc * 128 + c * 16;
            CP16(base + AHI_OFF + doff, (const char*)g_Xhi + abyt, 16);
            CP16(base + ALO_OFF + doff, (const char*)g_Xlo + abyt, 16);
            int n = n0 + r;
            int ok = (n < C_) ? 16 : 0;
            int nn = (n < C_) ? n : 0;
            size_t bbyt = (size_t)nn * (D_ * 2) + kc * 128 + c * 16;
            CP16(base + BHI_OFF + doff, (const char*)g_Whi + bbyt, ok);
            CP16(base + BLO_OFF + doff, (const char*)g_Wlo + bbyt, ok);
        }
    };

    auto compute_stage = [&](int st) {
        const uint32_t Ah = sb + st * STAGE_SZ + AHI_OFF;
        const uint32_t Al = sb + st * STAGE_SZ + ALO_OFF;
        const uint32_t Bh = sb + st * STAGE_SZ + BHI_OFF;
        const uint32_t Bl = sb + st * STAGE_SZ + BLO_OFF;
#pragma unroll
        for (int g = 0; g < 4; g++) {
            uint32_t ah[4][4], al[4][4];
#pragma unroll
            for (int i = 0; i < 4; i++) {
                uint32_t aoff = (uint32_t)((arow + 16 * i) * 128 + ((g * 32 + acol) ^ sx));
                LDSM4(ah[i], Ah + aoff);
                LDSM4(al[i], Al + aoff);
            }
            uint32_t bh[4][2], bl[4][2];
#pragma unroll
            for (int jp = 0; jp < 2; jp++) {
                uint32_t boff = (uint32_t)((brow + 16 * jp) * 128 + ((g * 32 + bcol) ^ sx));
                uint32_t t4[4];
                LDSM4(t4, Bh + boff);
                bh[2 * jp][0] = t4[0]; bh[2 * jp][1] = t4[1];
                bh[2 * jp + 1][0] = t4[2]; bh[2 * jp + 1][1] = t4[3];
                uint32_t u4[4];
                LDSM4(u4, Bl + boff);
                bl[2 * jp][0] = u4[0]; bl[2 * jp][1] = u4[1];
                bl[2 * jp + 1][0] = u4[2]; bl[2 * jp + 1][1] = u4[3];
            }
#pragma unroll
            for (int i = 0; i < 4; i++)
#pragma unroll
                for (int j = 0; j < 4; j++) {
                    MMA(acc[i][j], ah[i], bh[j]);
                    MMA(acc[i][j], ah[i], bl[j]);
                    MMA(acc[i][j], al[i], bh[j]);
                }
        }
    };

    load_stage(0, 0);
    asm volatile("cp.async.commit_group;" ::: "memory");
    load_stage(1, 1);
    asm volatile("cp.async.commit_group;" ::: "memory");
    load_stage(2, 2);
    asm volatile("cp.async.commit_group;" ::: "memory");

    for (int kc = 0; kc < 8; kc++) {
        asm volatile("cp.async.wait_group 2;" ::: "memory");
        __syncthreads();
        compute_stage(kc % 3);
        __syncthreads();
        if (kc + 3 < 8) load_stage(kc + 3, kc % 3);
        asm volatile("cp.async.commit_group;" ::: "memory");
    }

    // ---------------- epilogue: ArcFace + direct stores ----------------
#pragma unroll
    for (int i = 0; i < 4; i++) {
        int lm = mW + i * 16 + (lane >> 2);
        int gm = m0 + lm;
        int lab0 = slab[lm];
        int lab1 = slab[lm + 8];
#pragma unroll
        for (int j = 0; j < 4; j++) {
            int col = n0 + nW + j * 8 + (lane & 3) * 2;
            if (col < C_) {   // C_ even, pair stays in-bounds together
                float2 v0, v1;
                v0.x = arcf(acc[i][j][0], col == lab0);
                v0.y = arcf(acc[i][j][1], col + 1 == lab0);
                v1.x = arcf(acc[i][j][2], col == lab1);
                v1.y = arcf(acc[i][j][3], col + 1 == lab1);
                *reinterpret_cast<float2*>(out + (size_t)gm * C_ + col) = v0;
                *reinterpret_cast<float2*>(out + (size_t)(gm + 8) * C_ + col) = v1;
            }
        }
    }
    (void)pr;
}

// ---------------- launch ----------------
extern "C" void kernel_launch(void* const* d_in, const int* in_sizes, int n_in,
                              void* d_out, int out_size) {
    const float* X = nullptr;
    const float* W = nullptr;
    const void*  L = nullptr;

    for (int i = 0; i < n_in; i++) {
        int s = in_sizes[i];
        if (s == B_ * D_)      X = (const float*)d_in[i];
        else if (s == C_ * D_) W = (const float*)d_in[i];
        else if (s == B_)      L = d_in[i];
    }
    if (!X) X = (const float*)d_in[0];
    if (!L) L = d_in[1];
    if (!W) W = (const float*)d_in[2];

    float* out = (float*)d_out;

    decode_labels_kernel<<<1, 512>>>((const int*)L);
    xprep_kernel<<<B_, 128>>>(X);
    wprep_kernel<<<C_ / 2, 256>>>(W);

    cudaFuncSetAttribute(arcface_mma_kernel,
                         cudaFuncAttributeMaxDynamicSharedMemorySize, SMEM_TOTAL);
    dim3 grid(4, (C_ + 127) / 128);   // x = m-tile (fast) for W L2 reuse
    arcface_mma_kernel<<<grid, 256, SMEM_TOTAL>>>(out);
    (void)out_size;
}

// round 4
// speedup vs baseline: 7.1816x; 2.2133x over previous
#include <cuda_runtime.h>
#include <cuda_fp16.h>
#include <math.h>
#include <stdint.h>

// ---------------- problem constants ----------------
#define B_ 512
#define D_ 512
#define C_ 100000

#define S_F    30.0f
#define COSM_F 0.8775825618903728f
#define SINM_F 0.479425538604203f
#define TH_F  (-0.8775825618903728f)
#define MM_F   0.2397127693021015f

// ---------------- device scratch (static globals: allowed) ----------------
__device__ __half g_Xh[B_ * D_];
__device__ __half g_Wh[(size_t)C_ * D_];
__device__ int g_label[B_];

// ---------------- helpers ----------------
__device__ __forceinline__ uint32_t smem_u32(const void* p) {
    uint32_t a;
    asm("{ .reg .u64 t; cvta.to.shared.u64 t, %1; cvt.u32.u64 %0, t; }" : "=r"(a) : "l"(p));
    return a;
}

#define CP16(sm, gp, sz) \
    asm volatile("cp.async.cg.shared.global [%0], [%1], 16, %2;" \
                 :: "r"(sm), "l"(gp), "r"(sz) : "memory")

#define LDSM4(r, addr) \
    asm volatile("ldmatrix.sync.aligned.m8n8.x4.shared.b16 {%0,%1,%2,%3}, [%4];" \
                 : "=r"((r)[0]), "=r"((r)[1]), "=r"((r)[2]), "=r"((r)[3]) : "r"(addr))

#define MMA(acc, a, b) \
    asm volatile("mma.sync.aligned.m16n8k16.row.col.f32.f16.f16.f32 " \
                 "{%0,%1,%2,%3},{%4,%5,%6,%7},{%8,%9},{%0,%1,%2,%3};" \
                 : "+f"((acc)[0]), "+f"((acc)[1]), "+f"((acc)[2]), "+f"((acc)[3]) \
                 : "r"((a)[0]), "r"((a)[1]), "r"((a)[2]), "r"((a)[3]), \
                   "r"((b)[0]), "r"((b)[1]))

__device__ __forceinline__ float arcf(float c, bool isl) {
    c = fminf(1.0f, fmaxf(-1.0f, c));
    float s2 = fminf(1.0f, fmaxf(1e-9f, 1.0f - c * c));
    float sn;
    asm("sqrt.approx.f32 %0, %1;" : "=f"(sn) : "f"(s2));
    float phi = c * COSM_F - sn * SINM_F;
    phi = (c > TH_F) ? phi : (c - MM_F);
    return (isl ? phi : c) * S_F;
}

// ---------------- label decode (int64 or int32 layout) ----------------
__global__ void decode_labels_kernel(const int* __restrict__ raw) {
    __shared__ int any_odd_nonzero;
    int t = threadIdx.x;  // 512
    if (t == 0) any_odd_nonzero = 0;
    __syncthreads();
    int w = raw[t];
    if ((t & 1) && (w != 0)) any_odd_nonzero = 1;
    __syncthreads();
    g_label[t] = any_odd_nonzero ? raw[t] : raw[2 * t];
}

// ---------------- X: normalize + fp16 convert ----------------
__global__ void xprep_kernel(const float* __restrict__ X) {
    int row = blockIdx.x;
    int t = threadIdx.x;  // 128
    const float4* xf = reinterpret_cast<const float4*>(X + (size_t)row * D_);
    float4 v = xf[t];
    float s = v.x * v.x + v.y * v.y + v.z * v.z + v.w * v.w;
#pragma unroll
    for (int o = 16; o > 0; o >>= 1) s += __shfl_xor_sync(0xffffffffu, s, o);
    __shared__ float ws[4];
    if ((t & 31) == 0) ws[t >> 5] = s;
    __syncthreads();
    float tot = ws[0] + ws[1] + ws[2] + ws[3];
    float inv = 1.0f / fmaxf(sqrtf(tot), 1e-12f);
    __half2 h0 = __floats2half2_rn(v.x * inv, v.y * inv);
    __half2 h1 = __floats2half2_rn(v.z * inv, v.w * inv);
    __half2* dst = reinterpret_cast<__half2*>(g_Xh + (size_t)row * D_ + t * 4);
    dst[0] = h0;
    dst[1] = h1;
}

// ---------------- W: normalize + fp16 convert (2 rows per block) ----------
__global__ __launch_bounds__(256)
void wprep_kernel(const float* __restrict__ W) {
    int h = threadIdx.x >> 7;          // 0/1: which row
    int t = threadIdx.x & 127;         // 128 threads per row
    int row = blockIdx.x * 2 + h;      // C_ even, grid = C_/2 -> always valid
    const float4* wf = reinterpret_cast<const float4*>(W + (size_t)row * D_);
    float4 v = wf[t];
    float s = v.x * v.x + v.y * v.y + v.z * v.z + v.w * v.w;
#pragma unroll
    for (int o = 16; o > 0; o >>= 1) s += __shfl_xor_sync(0xffffffffu, s, o);
    __shared__ float ws[8];
    if ((t & 31) == 0) ws[h * 4 + (t >> 5)] = s;
    __syncthreads();
    float tot = ws[h * 4 + 0] + ws[h * 4 + 1] + ws[h * 4 + 2] + ws[h * 4 + 3];
    float inv = 1.0f / fmaxf(sqrtf(tot), 1e-12f);
    __half2 h0 = __floats2half2_rn(v.x * inv, v.y * inv);
    __half2 h1 = __floats2half2_rn(v.z * inv, v.w * inv);
    __half2* dst = reinterpret_cast<__half2*>(g_Wh + (size_t)row * D_ + t * 4);
    dst[0] = h0;
    dst[1] = h1;
}

// ---------------- GEMM + ArcFace (single-product fp16 mma.sync) -----------
// CTA 128x128, BK=64 fp16 (128B rows, SW128 swizzle), 3-stage cp.async,
// 2 CTAs/SM (96KB smem, <=128 regs).
#define A_OFF 0
#define B_OFF 16384
#define STAGE_SZ 32768
#define NSTAGE 3
#define SMEM_TOTAL (NSTAGE * STAGE_SZ)   // 98304

__global__ __launch_bounds__(256, 2)
void arcface_mma_kernel(float* __restrict__ out) {
    extern __shared__ char Smem[];
    __shared__ int slab[128];
    const uint32_t sb = smem_u32(Smem);
    const int tid = threadIdx.x;
    const int lane = tid & 31;
    const int wid = tid >> 5;
    const int m0 = blockIdx.x * 128;   // x fastest -> 4 m-tiles share W n-tile in L2
    const int n0 = blockIdx.y * 128;
    const int mW = (wid >> 2) * 64;    // warp tile 64x32
    const int nW = (wid & 3) * 32;

    if (tid < 128) slab[tid] = g_label[m0 + tid];

    float acc[4][4][4];
#pragma unroll
    for (int i = 0; i < 4; i++)
#pragma unroll
        for (int j = 0; j < 4; j++)
#pragma unroll
            for (int q = 0; q < 4; q++) acc[i][j][q] = 0.0f;

    // ldmatrix lane-address components (same mapping as validated round 3)
    const int arow = mW + (lane & 7) + ((lane >> 3) & 1) * 8;   // + 16*i
    const int acol = ((lane >> 4) & 1) * 16;                    // + 32*g
    const int brow = nW + ((lane >> 4) & 1) * 8 + (lane & 7);   // + 16*jp
    const int bcol = ((lane >> 3) & 1) * 16;
    const int sx   = (lane & 7) * 16;                           // swizzle xor

    auto load_stage = [&](int kc, int st) {
        uint32_t base = sb + st * STAGE_SZ;
#pragma unroll
        for (int j = 0; j < 4; j++) {
            int idx = tid + 256 * j;
            int r = idx >> 3, c = idx & 7;
            uint32_t doff = (uint32_t)(r * 128 + ((c * 16) ^ ((r & 7) * 16)));
            size_t abyt = (size_t)(m0 + r) * (D_ * 2) + kc * 128 + c * 16;
            CP16(base + A_OFF + doff, (const char*)g_Xh + abyt, 16);
            int n = n0 + r;
            int ok = (n < C_) ? 16 : 0;
            int nn = (n < C_) ? n : 0;
            size_t bbyt = (size_t)nn * (D_ * 2) + kc * 128 + c * 16;
            CP16(base + B_OFF + doff, (const char*)g_Wh + bbyt, ok);
        }
    };

    auto compute_stage = [&](int st) {
        const uint32_t Ab = sb + st * STAGE_SZ + A_OFF;
        const uint32_t Bb = sb + st * STAGE_SZ + B_OFF;
#pragma unroll
        for (int g = 0; g < 4; g++) {
            uint32_t ah[4][4];
#pragma unroll
            for (int i = 0; i < 4; i++) {
                uint32_t aoff = (uint32_t)((arow + 16 * i) * 128 + ((g * 32 + acol) ^ sx));
                LDSM4(ah[i], Ab + aoff);
            }
            uint32_t bh[4][2];
#pragma unroll
            for (int jp = 0; jp < 2; jp++) {
                uint32_t boff = (uint32_t)((brow + 16 * jp) * 128 + ((g * 32 + bcol) ^ sx));
                uint32_t t4[4];
                LDSM4(t4, Bb + boff);
                bh[2 * jp][0] = t4[0]; bh[2 * jp][1] = t4[1];
                bh[2 * jp + 1][0] = t4[2]; bh[2 * jp + 1][1] = t4[3];
            }
#pragma unroll
            for (int i = 0; i < 4; i++)
#pragma unroll
                for (int j = 0; j < 4; j++) MMA(acc[i][j], ah[i], bh[j]);
        }
    };

    load_stage(0, 0);
    asm volatile("cp.async.commit_group;" ::: "memory");
    load_stage(1, 1);
    asm volatile("cp.async.commit_group;" ::: "memory");
    load_stage(2, 2);
    asm volatile("cp.async.commit_group;" ::: "memory");

    for (int kc = 0; kc < 8; kc++) {
        asm volatile("cp.async.wait_group 2;" ::: "memory");
        __syncthreads();
        compute_stage(kc % 3);
        __syncthreads();
        if (kc + 3 < 8) load_stage(kc + 3, kc % 3);
        asm volatile("cp.async.commit_group;" ::: "memory");
    }

    // ---------------- epilogue: ArcFace + direct stores ----------------
#pragma unroll
    for (int i = 0; i < 4; i++) {
        int lm = mW + i * 16 + (lane >> 2);
        int gm = m0 + lm;
        int lab0 = slab[lm];
        int lab1 = slab[lm + 8];
#pragma unroll
        for (int j = 0; j < 4; j++) {
            int col = n0 + nW + j * 8 + (lane & 3) * 2;
            if (col < C_) {   // C_ even -> pair stays in-bounds together
                float2 v0, v1;
                v0.x = arcf(acc[i][j][0], col == lab0);
                v0.y = arcf(acc[i][j][1], col + 1 == lab0);
                v1.x = arcf(acc[i][j][2], col == lab1);
                v1.y = arcf(acc[i][j][3], col + 1 == lab1);
                *reinterpret_cast<float2*>(out + (size_t)gm * C_ + col) = v0;
                *reinterpret_cast<float2*>(out + (size_t)(gm + 8) * C_ + col) = v1;
            }
        }
    }
}

// ---------------- launch ----------------
extern "C" void kernel_launch(void* const* d_in, const int* in_sizes, int n_in,
                              void* d_out, int out_size) {
    const float* X = nullptr;
    const float* W = nullptr;
    const void*  L = nullptr;

    for (int i = 0; i < n_in; i++) {
        int s = in_sizes[i];
        if (s == B_ * D_)      X = (const float*)d_in[i];
        else if (s == C_ * D_) W = (const float*)d_in[i];
        else if (s == B_)      L = d_in[i];
    }
    if (!X) X = (const float*)d_in[0];
    if (!L) L = d_in[1];
    if (!W) W = (const float*)d_in[2];

    float* out = (float*)d_out;

    decode_labels_kernel<<<1, 512>>>((const int*)L);
    xprep_kernel<<<B_, 128>>>(X);
    wprep_kernel<<<C_ / 2, 256>>>(W);

    cudaFuncSetAttribute(arcface_mma_kernel,
                         cudaFuncAttributeMaxDynamicSharedMemorySize, SMEM_TOTAL);
    dim3 grid(4, (C_ + 127) / 128);   // x = m-tile (fast) for W L2 reuse
    arcface_mma_kernel<<<grid, 256, SMEM_TOTAL>>>(out);
    (void)out_size;
}